// round 2
// baseline (speedup 1.0000x reference)
#include <cuda_runtime.h>
#include <math.h>

// Problem constants
#define B_    4
#define C_    180
#define H_    256
#define W_    256
#define HW_   65536
#define NPIX  262144      // B*H*W
#define HEADS_ 6
#define HD_   30
#define HID_  360
#define KV_C  90

// ---------------- static scratch (no allocations allowed) ----------------
__device__ float g_kvm[B_ * 2 * C_];
__device__ float g_kvf[B_ * 2 * C_];
__device__ float g_yw [(size_t)NPIX * C_];     // LN1+FiLM out, pixel-major
__device__ float g_q  [(size_t)NPIX * C_];     // q projection
__device__ float g_kv [(size_t)NPIX * KV_C];   // kv projection
__device__ float g_ao [(size_t)NPIX * C_];     // attention out (pre-proj)
__device__ float g_x2 [(size_t)NPIX * C_];     // x + attn (NCHW)
__device__ float g_y2 [(size_t)NPIX * C_];     // LN2+FiLM out, pixel-major
__device__ float g_t  [(size_t)NPIX * 2 * HID_]; // pin out (720 ch)
__device__ float g_g  [(size_t)NPIX * HID_];   // gated (360 ch)

// ---------------- FiLM coefficients: kvm = k_v @ W^T ----------------
__global__ void film_kernel(const float* __restrict__ kvv,
                            const float* __restrict__ wA,
                            const float* __restrict__ wF) {
    int b = blockIdx.x, j = threadIdx.x;   // j in [0,360)
    const float* kb = kvv + b * 256;
    const float* ra = wA + (size_t)j * 256;
    const float* rf = wF + (size_t)j * 256;
    float sA = 0.f, sF = 0.f;
    for (int i = 0; i < 256; i++) {
        float t = kb[i];
        sA = fmaf(t, ra[i], sA);
        sF = fmaf(t, rf[i], sF);
    }
    g_kvm[b * 360 + j] = sA;
    g_kvf[b * 360 + j] = sF;
}

// ---------------- LayerNorm (channel dim, NCHW in) + FiLM -> pixel-major out
__global__ void ln_film_kernel(const float* __restrict__ x,
                               const float* __restrict__ lw,
                               const float* __restrict__ lb,
                               int which,
                               float* __restrict__ out) {
    int pix = blockIdx.x * blockDim.x + threadIdx.x;
    int b = pix >> 16;
    int s = pix & 0xFFFF;
    const float* xb = x + (size_t)b * C_ * HW_ + s;
    float sum = 0.f, sq = 0.f;
    for (int c = 0; c < C_; c++) {
        float v = xb[(size_t)c * HW_];
        sum += v;
        sq = fmaf(v, v, sq);
    }
    float mu  = sum * (1.0f / C_);
    float var = sq * (1.0f / C_) - mu * mu;
    float inv = rsqrtf(var + 1e-5f);
    const float* fb = (which ? g_kvf : g_kvm) + b * 2 * C_;
    float4* op = reinterpret_cast<float4*>(out + (size_t)pix * C_);
#pragma unroll 5
    for (int c4 = 0; c4 < C_ / 4; c4++) {
        float4 r;
        float* rp = reinterpret_cast<float*>(&r);
#pragma unroll
        for (int u = 0; u < 4; u++) {
            int c = c4 * 4 + u;
            float v = xb[(size_t)c * HW_];
            float yn = (v - mu) * inv * lw[c] + lb[c];
            rp[u] = fmaf(yn, fb[c], fb[C_ + c]);
        }
        op[c4] = r;
    }
}

// ---------------- fp32 tiled GEMM:  Y[M,N] = X[M,K] @ W[N,K]^T (+bias) ------
// RES=0: Y pixel-major [m*N+n].   RES=1: Y/res in NCHW (N must be 180).
#define BM 128
#define BN 64
#define BK 16

template <int RES>
__global__ void gemm_kernel(const float* __restrict__ X,
                            const float* __restrict__ Wt,
                            const float* __restrict__ bias,
                            const float* __restrict__ res,
                            float* __restrict__ Y,
                            int N, int K) {
    __shared__ __align__(16) float As[BK][BM];
    __shared__ __align__(16) float Bs[BK][BN];
    int m0 = blockIdx.x * BM;
    int n0 = blockIdx.y * BN;
    int t  = threadIdx.x;             // 256 threads
    int tx = t & 15, ty = t >> 4;

    float acc[8][4];
#pragma unroll
    for (int i = 0; i < 8; i++)
#pragma unroll
        for (int j = 0; j < 4; j++) acc[i][j] = 0.f;

    int arow = t >> 1, akb = (t & 1) * 8;     // A: 128 rows x 16 k, 8/thread
    int brow = t >> 2, bkb = (t & 3) * 4;     // B: 64 rows x 16 k, 4/thread

    for (int kk = 0; kk < K; kk += BK) {
        const float* xp = X + (size_t)(m0 + arow) * K + kk + akb;
#pragma unroll
        for (int u = 0; u < 8; u++)
            As[akb + u][arow] = (kk + akb + u < K) ? xp[u] : 0.f;

        bool bvalid = (n0 + brow) < N;
        const float* wp = Wt + (size_t)(n0 + brow) * K + kk + bkb;
#pragma unroll
        for (int u = 0; u < 4; u++)
            Bs[bkb + u][brow] = (bvalid && (kk + bkb + u < K)) ? wp[u] : 0.f;

        __syncthreads();
#pragma unroll
        for (int k = 0; k < BK; k++) {
            float4 b4 = *reinterpret_cast<const float4*>(&Bs[k][tx * 4]);
            float4 a0 = *reinterpret_cast<const float4*>(&As[k][ty * 8]);
            float4 a1 = *reinterpret_cast<const float4*>(&As[k][ty * 8 + 4]);
            float aa[8] = {a0.x, a0.y, a0.z, a0.w, a1.x, a1.y, a1.z, a1.w};
            float bb[4] = {b4.x, b4.y, b4.z, b4.w};
#pragma unroll
            for (int i = 0; i < 8; i++)
#pragma unroll
                for (int j = 0; j < 4; j++)
                    acc[i][j] = fmaf(aa[i], bb[j], acc[i][j]);
        }
        __syncthreads();
    }

#pragma unroll
    for (int i = 0; i < 8; i++) {
        int m = m0 + ty * 8 + i;
#pragma unroll
        for (int j = 0; j < 4; j++) {
            int n = n0 + tx * 4 + j;
            if (n < N) {
                float v = acc[i][j];
                if (bias) v += bias[n];
                if (RES) {
                    int b = m >> 16, s = m & 0xFFFF;
                    size_t idx = ((size_t)b * C_ + n) * HW_ + s;
                    Y[idx] = res[idx] + v;
                } else {
                    Y[(size_t)m * N + n] = v;
                }
            }
        }
    }
}

// ---------------- Windowed attention, one CTA per 16x16 window --------------
// k/v gathered into smem in permuted-head layout:
//   channel idx = h*30+d -> (i = idx/90, j = (idx/45)&1, c4 = idx%45)
//   group g = p1*8+p2 maps to pixel (p1*2+i, p2*2+j) inside the window.
__global__ void attn_kernel(const float* __restrict__ qbuf,
                            const float* __restrict__ kvbuf,
                            const float* __restrict__ rel,
                            float* __restrict__ out) {
    extern __shared__ float sm[];
    float* ks = sm;                        // [6][64][30]
    float* vs = sm + HEADS_ * 64 * HD_;    // [6][64][30]

    int wb = blockIdx.x;                   // 0..1023
    int b  = wb >> 8;
    int wi = wb & 255;
    int wy = wi >> 4, wx = wi & 15;
    int t  = threadIdx.x;                  // 256

    for (int e = t; e < HEADS_ * 64 * HD_; e += 256) {
        int h = e / (64 * HD_);
        int r = e - h * 64 * HD_;
        int g = r / HD_;
        int d = r - g * HD_;
        int idx = h * HD_ + d;
        int ii = idx / 90;
        int jj = (idx / 45) & 1;
        int c4 = idx % 45;
        int p1 = g >> 3, p2 = g & 7;
        int hh = wy * 16 + p1 * 2 + ii;
        int ww = wx * 16 + p2 * 2 + jj;
        size_t pix = ((size_t)b * H_ + hh) * W_ + ww;
        ks[e] = kvbuf[pix * KV_C + c4];
        vs[e] = kvbuf[pix * KV_C + 45 + c4];
    }
    __syncthreads();

    int rr = t >> 4, cc = t & 15;
    int hh = wy * 16 + rr, ww = wx * 16 + cc;
    size_t pix = ((size_t)b * H_ + hh) * W_ + ww;
    int ah = rr >> 1, aw = cc >> 1;
    const float scale = 0.18257418583505536f;   // 30^-0.5

    float lg[64];
    for (int h = 0; h < HEADS_; h++) {
        float qv[HD_];
        const float* qp = qbuf + pix * C_ + h * HD_;
#pragma unroll
        for (int d = 0; d < HD_; d++) qv[d] = qp[d] * scale;

        float mx = -1e30f;
        const float* kh = ks + h * 64 * HD_;
#pragma unroll
        for (int g = 0; g < 64; g++) {
            float s2 = 0.f;
            const float* kg = kh + g * HD_;
#pragma unroll
            for (int d = 0; d < HD_; d++) s2 = fmaf(qv[d], kg[d], s2);
            int gh = g >> 3, gw = g & 7;
            s2 += rel[((ah - gh + 7) * 15 + (aw - gw + 7)) * HEADS_ + h];
            lg[g] = s2;
            mx = fmaxf(mx, s2);
        }
        float den = 0.f;
#pragma unroll
        for (int g = 0; g < 64; g++) {
            float e2 = __expf(lg[g] - mx);
            lg[g] = e2;
            den += e2;
        }
        float o[HD_];
#pragma unroll
        for (int d = 0; d < HD_; d++) o[d] = 0.f;
        const float* vh = vs + h * 64 * HD_;
#pragma unroll
        for (int g = 0; g < 64; g++) {
            float p = lg[g];
            const float* vg = vh + g * HD_;
#pragma unroll
            for (int d = 0; d < HD_; d++) o[d] = fmaf(p, vg[d], o[d]);
        }
        float rdn = 1.f / den;
        float* op = out + pix * C_ + h * HD_;
#pragma unroll
        for (int d = 0; d < HD_; d++) op[d] = o[d] * rdn;
    }
}

// ---------------- depthwise 3x3 (cross-correlation) + exact GELU gate -------
__global__ void dwgate_kernel(const float* __restrict__ tbuf,
                              const float* __restrict__ wdw,
                              float* __restrict__ gbuf) {
    int pix = blockIdx.x;
    int c   = threadIdx.x;       // 0..359
    int b  = pix >> 16;
    int s  = pix & 0xFFFF;
    int hh = s >> 8;
    int ww = s & 255;
    float a = 0.f, bv = 0.f;
    const float* wa = wdw + (size_t)c * 9;
    const float* wb = wdw + (size_t)(c + HID_) * 9;
#pragma unroll
    for (int ky = 0; ky < 3; ky++) {
        int y = hh + ky - 1;
        if ((unsigned)y >= H_) continue;
#pragma unroll
        for (int kx = 0; kx < 3; kx++) {
            int xw = ww + kx - 1;
            if ((unsigned)xw >= W_) continue;
            size_t np = (((size_t)b * H_ + y) * W_ + xw) * (2 * HID_);
            a  = fmaf(tbuf[np + c],        wa[ky * 3 + kx], a);
            bv = fmaf(tbuf[np + HID_ + c], wb[ky * 3 + kx], bv);
        }
    }
    float ge = 0.5f * a * (1.f + erff(a * 0.7071067811865475f));
    gbuf[(size_t)pix * HID_ + c] = ge * bv;
}

// ---------------- host launcher ----------------
extern "C" void kernel_launch(void* const* d_in, const int* in_sizes, int n_in,
                              void* d_out, int out_size) {
    const float* x        = (const float*)d_in[0];
    const float* k_v      = (const float*)d_in[1];
    const float* ln1_w    = (const float*)d_in[2];
    const float* ln1_b    = (const float*)d_in[3];
    const float* ln2_w    = (const float*)d_in[4];
    const float* ln2_b    = (const float*)d_in[5];
    const float* w_kern_a = (const float*)d_in[6];
    const float* rel      = (const float*)d_in[7];
    const float* w_kv     = (const float*)d_in[8];
    const float* b_kv     = (const float*)d_in[9];
    const float* w_q      = (const float*)d_in[10];
    const float* b_q      = (const float*)d_in[11];
    const float* w_proj   = (const float*)d_in[12];
    const float* b_proj   = (const float*)d_in[13];
    const float* w_kern_f = (const float*)d_in[14];
    const float* w_pin    = (const float*)d_in[15];
    const float* w_dw     = (const float*)d_in[16];
    const float* w_pout   = (const float*)d_in[17];
    float* outp = (float*)d_out;

    float *p_yw, *p_q, *p_kv, *p_ao, *p_x2, *p_y2, *p_t, *p_g;
    cudaGetSymbolAddress((void**)&p_yw, g_yw);
    cudaGetSymbolAddress((void**)&p_q,  g_q);
    cudaGetSymbolAddress((void**)&p_kv, g_kv);
    cudaGetSymbolAddress((void**)&p_ao, g_ao);
    cudaGetSymbolAddress((void**)&p_x2, g_x2);
    cudaGetSymbolAddress((void**)&p_y2, g_y2);
    cudaGetSymbolAddress((void**)&p_t,  g_t);
    cudaGetSymbolAddress((void**)&p_g,  g_g);

    cudaFuncSetAttribute(attn_kernel,
                         cudaFuncAttributeMaxDynamicSharedMemorySize,
                         2 * HEADS_ * 64 * HD_ * (int)sizeof(float));

    // 1) FiLM coefficients
    film_kernel<<<B_, 360>>>(k_v, w_kern_a, w_kern_f);

    // 2) LN1 + FiLM  (NCHW -> pixel-major)
    ln_film_kernel<<<NPIX / 256, 256>>>(x, ln1_w, ln1_b, 0, p_yw);

    // 3) q / kv projections
    dim3 gq(NPIX / BM, (180 + BN - 1) / BN);
    gemm_kernel<0><<<gq, 256>>>(p_yw, w_q, b_q, nullptr, p_q, 180, 180);
    dim3 gkv(NPIX / BM, (90 + BN - 1) / BN);
    gemm_kernel<0><<<gkv, 256>>>(p_yw, w_kv, b_kv, nullptr, p_kv, 90, 180);

    // 4) windowed attention
    attn_kernel<<<1024, 256, 2 * HEADS_ * 64 * HD_ * (int)sizeof(float)>>>(
        p_q, p_kv, rel, p_ao);

    // 5) proj + residual -> x2 (NCHW)
    gemm_kernel<1><<<gq, 256>>>(p_ao, w_proj, b_proj, x, p_x2, 180, 180);

    // 6) LN2 + FiLM
    ln_film_kernel<<<NPIX / 256, 256>>>(p_x2, ln2_w, ln2_b, 1, p_y2);

    // 7) pin (1x1 conv, N=720)
    dim3 gp(NPIX / BM, (720 + BN - 1) / BN);
    gemm_kernel<0><<<gp, 256>>>(p_y2, w_pin, nullptr, nullptr, p_t, 720, 180);

    // 8) depthwise 3x3 + GELU gate
    dwgate_kernel<<<NPIX, HID_>>>(p_t, w_dw, p_g);

    // 9) pout + residual -> d_out (NCHW)
    gemm_kernel<1><<<gq, 256>>>(p_g, w_pout, nullptr, p_x2, outp, 180, 360);
}

// round 9
// speedup vs baseline: 1.5273x; 1.5273x over previous
#include <cuda_runtime.h>
#include <math.h>
#include <mma.h>

using namespace nvcuda;

// Problem constants
#define B_    4
#define C_    180
#define H_    256
#define W_    256
#define HW_   65536
#define NPIX  262144      // B*H*W
#define HEADS_ 6
#define HD_   30
#define HID_  360
#define KV_C  90

// ---------------- static scratch (no allocations allowed) ----------------
__device__ float g_kvm[B_ * 2 * C_];
__device__ float g_kvf[B_ * 2 * C_];
__device__ float g_yw [(size_t)NPIX * C_];     // LN1+FiLM out, pixel-major
__device__ float g_q  [(size_t)NPIX * C_];     // q projection
__device__ float g_kv [(size_t)NPIX * KV_C];   // kv projection
__device__ float g_ao [(size_t)NPIX * C_];     // attention out (pre-proj)
__device__ float g_x2 [(size_t)NPIX * C_];     // x + attn (NCHW)
__device__ float g_y2 [(size_t)NPIX * C_];     // LN2+FiLM out, pixel-major
__device__ float g_t  [(size_t)NPIX * 2 * HID_]; // pin out (720 ch)
__device__ float g_g  [(size_t)NPIX * HID_];   // gated (360 ch)

// ---------------- FiLM coefficients: kvm = k_v @ W^T ----------------
__global__ void film_kernel(const float* __restrict__ kvv,
                            const float* __restrict__ wA,
                            const float* __restrict__ wF) {
    int b = blockIdx.x, j = threadIdx.x;   // j in [0,360)
    const float* kb = kvv + b * 256;
    const float* ra = wA + (size_t)j * 256;
    const float* rf = wF + (size_t)j * 256;
    float sA = 0.f, sF = 0.f;
    for (int i = 0; i < 256; i++) {
        float t = kb[i];
        sA = fmaf(t, ra[i], sA);
        sF = fmaf(t, rf[i], sF);
    }
    g_kvm[b * 360 + j] = sA;
    g_kvf[b * 360 + j] = sF;
}

// ---------------- LayerNorm (channel dim, NCHW in) + FiLM -> pixel-major out
__global__ void ln_film_kernel(const float* __restrict__ x,
                               const float* __restrict__ lw,
                               const float* __restrict__ lb,
                               int which,
                               float* __restrict__ out) {
    int pix = blockIdx.x * blockDim.x + threadIdx.x;
    int b = pix >> 16;
    int s = pix & 0xFFFF;
    const float* xb = x + (size_t)b * C_ * HW_ + s;
    float sum = 0.f, sq = 0.f;
    for (int c = 0; c < C_; c++) {
        float v = xb[(size_t)c * HW_];
        sum += v;
        sq = fmaf(v, v, sq);
    }
    float mu  = sum * (1.0f / C_);
    float var = sq * (1.0f / C_) - mu * mu;
    float inv = rsqrtf(var + 1e-5f);
    const float* fb = (which ? g_kvf : g_kvm) + b * 2 * C_;
    float4* op = reinterpret_cast<float4*>(out + (size_t)pix * C_);
#pragma unroll 5
    for (int c4 = 0; c4 < C_ / 4; c4++) {
        float4 r;
        float* rp = reinterpret_cast<float*>(&r);
#pragma unroll
        for (int u = 0; u < 4; u++) {
            int c = c4 * 4 + u;
            float v = xb[(size_t)c * HW_];
            float yn = (v - mu) * inv * lw[c] + lb[c];
            rp[u] = fmaf(yn, fb[c], fb[C_ + c]);
        }
        op[c4] = r;
    }
}

// ---------------- tf32 tensor-core GEMM: Y[M,N] = X[M,K] @ W[N,K]^T (+bias)
// BM=128, BN=64, BK=16. 256 threads = 8 warps in 4(M) x 2(N) grid,
// each warp computes 2x2 fragments of 16x16.
// RES=0: Y pixel-major [m*N+n].  RES=1: Y = res + v, both NCHW.
#define GBM 128
#define GBN 64
#define GBK 16
#define APAD 20           // row stride (floats) for As/Bs, 80B = 16B-aligned
#define CPAD 72           // row stride for C stage

template <int RES>
__global__ void __launch_bounds__(256)
gemm_tc(const float* __restrict__ X,
        const float* __restrict__ Wt,
        const float* __restrict__ bias,
        const float* __restrict__ res,
        float* __restrict__ Y,
        int N, int K) {
    __shared__ __align__(16) float sm_[GBM * CPAD];   // 36.9 KB, reused for C
    float* As = sm_;                    // [128][APAD]
    float* Bs = sm_ + GBM * APAD;       // [64][APAD]

    const int t  = threadIdx.x;
    const int m0 = blockIdx.y * GBM;
    const int n0 = blockIdx.x * GBN;
    const int w  = t >> 5;
    const int wm = w >> 1;              // 0..3
    const int wn = w & 1;               // 0..1

    wmma::fragment<wmma::accumulator, 16, 16, 8, float> cf[2][2];
#pragma unroll
    for (int i = 0; i < 2; i++)
#pragma unroll
        for (int j = 0; j < 2; j++) wmma::fill_fragment(cf[i][j], 0.0f);

    const float4 z4 = make_float4(0.f, 0.f, 0.f, 0.f);
    const int br = t >> 2, bq = t & 3;               // B: 1 float4/thread
    const bool bvalid = (n0 + br) < N;

    for (int kk = 0; kk < K; kk += GBK) {
        // ---- A tile: 128x16 = 512 float4, 2 per thread ----
#pragma unroll
        for (int u = 0; u < 2; u++) {
            int idx = t * 2 + u;
            int r = idx >> 2, kq = idx & 3;
            float4 v = z4;
            if (kk + kq * 4 < K)
                v = *reinterpret_cast<const float4*>(
                        X + (size_t)(m0 + r) * K + kk + kq * 4);
            *reinterpret_cast<float4*>(As + r * APAD + kq * 4) = v;
        }
        // ---- B tile: 64x16 = 256 float4, 1 per thread ----
        {
            float4 v = z4;
            if (bvalid && (kk + bq * 4 < K))
                v = *reinterpret_cast<const float4*>(
                        Wt + (size_t)(n0 + br) * K + kk + bq * 4);
            *reinterpret_cast<float4*>(Bs + br * APAD + bq * 4) = v;
        }
        __syncthreads();

#pragma unroll
        for (int k0 = 0; k0 < GBK; k0 += 8) {
            wmma::fragment<wmma::matrix_a, 16, 16, 8,
                           wmma::precision::tf32, wmma::row_major> af[2];
            wmma::fragment<wmma::matrix_b, 16, 16, 8,
                           wmma::precision::tf32, wmma::col_major> bf[2];
#pragma unroll
            for (int i = 0; i < 2; i++) {
                wmma::load_matrix_sync(af[i],
                    As + (wm * 32 + i * 16) * APAD + k0, APAD);
#pragma unroll
                for (int e = 0; e < af[i].num_elements; e++)
                    af[i].x[e] = wmma::__float_to_tf32(af[i].x[e]);
            }
#pragma unroll
            for (int j = 0; j < 2; j++) {
                wmma::load_matrix_sync(bf[j],
                    Bs + (wn * 32 + j * 16) * APAD + k0, APAD);
#pragma unroll
                for (int e = 0; e < bf[j].num_elements; e++)
                    bf[j].x[e] = wmma::__float_to_tf32(bf[j].x[e]);
            }
#pragma unroll
            for (int i = 0; i < 2; i++)
#pragma unroll
                for (int j = 0; j < 2; j++)
                    wmma::mma_sync(cf[i][j], af[i], bf[j], cf[i][j]);
        }
        __syncthreads();
    }

    // ---- stage C through smem (reuses As/Bs region) ----
    float* Cs = sm_;
#pragma unroll
    for (int i = 0; i < 2; i++)
#pragma unroll
        for (int j = 0; j < 2; j++)
            wmma::store_matrix_sync(
                Cs + (wm * 32 + i * 16) * CPAD + wn * 32 + j * 16,
                cf[i][j], CPAD, wmma::mem_row_major);
    __syncthreads();

    // ---- epilogue: 128x64 elements ----
    if (RES) {
        // n-major traversal: consecutive threads -> consecutive m (coalesced NCHW)
#pragma unroll
        for (int i = 0; i < 32; i++) {
            int e = t + 256 * i;
            int nl = e >> 7, ml = e & 127;
            int n = n0 + nl;
            if (n < N) {
                int m = m0 + ml;
                int b = m >> 16, s = m & 0xFFFF;
                size_t idx = ((size_t)b * C_ + n) * HW_ + s;
                float v = Cs[ml * CPAD + nl];
                if (bias) v += bias[n];
                Y[idx] = res[idx] + v;
            }
        }
    } else if ((N & 3) == 0) {
        // m-major, float4-wide: rows are 16B-aligned only when N % 4 == 0
#pragma unroll
        for (int i = 0; i < 8; i++) {
            int e = t + 256 * i;
            int ml = e >> 4, nq = e & 15;          // nq: float4 index in row
            int n = n0 + nq * 4;
            if (n < N) {
                float4 v = *reinterpret_cast<const float4*>(
                               Cs + ml * CPAD + nq * 4);
                if (bias) {
                    v.x += bias[n];     v.y += bias[n + 1];
                    v.z += bias[n + 2]; v.w += bias[n + 3];
                }
                *reinterpret_cast<float4*>(Y + (size_t)(m0 + ml) * N + n) = v;
            }
        }
    } else {
        // scalar fallback (N = 90 kv projection)
#pragma unroll
        for (int i = 0; i < 32; i++) {
            int e = t + 256 * i;
            int ml = e >> 6, nl = e & 63;
            int n = n0 + nl;
            if (n < N) {
                float v = Cs[ml * CPAD + nl];
                if (bias) v += bias[n];
                Y[(size_t)(m0 + ml) * N + n] = v;
            }
        }
    }
}

// ---------------- Windowed attention, one CTA per 16x16 window --------------
__global__ void attn_kernel(const float* __restrict__ qbuf,
                            const float* __restrict__ kvbuf,
                            const float* __restrict__ rel,
                            float* __restrict__ out) {
    extern __shared__ float sm[];
    float* ks = sm;                        // [6][64][30]
    float* vs = sm + HEADS_ * 64 * HD_;    // [6][64][30]

    int wb = blockIdx.x;                   // 0..1023
    int b  = wb >> 8;
    int wi = wb & 255;
    int wy = wi >> 4, wx = wi & 15;
    int t  = threadIdx.x;                  // 256

    for (int e = t; e < HEADS_ * 64 * HD_; e += 256) {
        int h = e / (64 * HD_);
        int r = e - h * 64 * HD_;
        int g = r / HD_;
        int d = r - g * HD_;
        int idx = h * HD_ + d;
        int ii = idx / 90;
        int jj = (idx / 45) & 1;
        int c4 = idx % 45;
        int p1 = g >> 3, p2 = g & 7;
        int hh = wy * 16 + p1 * 2 + ii;
        int ww = wx * 16 + p2 * 2 + jj;
        size_t pix = ((size_t)b * H_ + hh) * W_ + ww;
        ks[e] = kvbuf[pix * KV_C + c4];
        vs[e] = kvbuf[pix * KV_C + 45 + c4];
    }
    __syncthreads();

    int rr = t >> 4, cc = t & 15;
    int hh = wy * 16 + rr, ww = wx * 16 + cc;
    size_t pix = ((size_t)b * H_ + hh) * W_ + ww;
    int ah = rr >> 1, aw = cc >> 1;
    const float scale = 0.18257418583505536f;   // 30^-0.5

    float lg[64];
    for (int h = 0; h < HEADS_; h++) {
        float qv[HD_];
        const float* qp = qbuf + pix * C_ + h * HD_;
#pragma unroll
        for (int d = 0; d < HD_; d++) qv[d] = qp[d] * scale;

        float mx = -1e30f;
        const float* kh = ks + h * 64 * HD_;
#pragma unroll
        for (int g = 0; g < 64; g++) {
            float s2 = 0.f;
            const float* kg = kh + g * HD_;
#pragma unroll
            for (int d = 0; d < HD_; d++) s2 = fmaf(qv[d], kg[d], s2);
            int gh = g >> 3, gw = g & 7;
            s2 += rel[((ah - gh + 7) * 15 + (aw - gw + 7)) * HEADS_ + h];
            lg[g] = s2;
            mx = fmaxf(mx, s2);
        }
        float den = 0.f;
#pragma unroll
        for (int g = 0; g < 64; g++) {
            float e2 = __expf(lg[g] - mx);
            lg[g] = e2;
            den += e2;
        }
        float o[HD_];
#pragma unroll
        for (int d = 0; d < HD_; d++) o[d] = 0.f;
        const float* vh = vs + h * 64 * HD_;
#pragma unroll
        for (int g = 0; g < 64; g++) {
            float p = lg[g];
            const float* vg = vh + g * HD_;
#pragma unroll
            for (int d = 0; d < HD_; d++) o[d] = fmaf(p, vg[d], o[d]);
        }
        float rdn = 1.f / den;
        float* op = out + pix * C_ + h * HD_;
#pragma unroll
        for (int d = 0; d < HD_; d++) op[d] = o[d] * rdn;
    }
}

// ---------------- depthwise 3x3 (cross-correlation) + exact GELU gate -------
__global__ void dwgate_kernel(const float* __restrict__ tbuf,
                              const float* __restrict__ wdw,
                              float* __restrict__ gbuf) {
    int pix = blockIdx.x;
    int c   = threadIdx.x;       // 0..359
    int b  = pix >> 16;
    int s  = pix & 0xFFFF;
    int hh = s >> 8;
    int ww = s & 255;
    float a = 0.f, bv = 0.f;
    const float* wa = wdw + (size_t)c * 9;
    const float* wb = wdw + (size_t)(c + HID_) * 9;
#pragma unroll
    for (int ky = 0; ky < 3; ky++) {
        int y = hh + ky - 1;
        if ((unsigned)y >= H_) continue;
#pragma unroll
        for (int kx = 0; kx < 3; kx++) {
            int xw = ww + kx - 1;
            if ((unsigned)xw >= W_) continue;
            size_t np = (((size_t)b * H_ + y) * W_ + xw) * (2 * HID_);
            a  = fmaf(tbuf[np + c],        wa[ky * 3 + kx], a);
            bv = fmaf(tbuf[np + HID_ + c], wb[ky * 3 + kx], bv);
        }
    }
    float ge = 0.5f * a * (1.f + erff(a * 0.7071067811865475f));
    gbuf[(size_t)pix * HID_ + c] = ge * bv;
}

// ---------------- host launcher ----------------
extern "C" void kernel_launch(void* const* d_in, const int* in_sizes, int n_in,
                              void* d_out, int out_size) {
    const float* x        = (const float*)d_in[0];
    const float* k_v      = (const float*)d_in[1];
    const float* ln1_w    = (const float*)d_in[2];
    const float* ln1_b    = (const float*)d_in[3];
    const float* ln2_w    = (const float*)d_in[4];
    const float* ln2_b    = (const float*)d_in[5];
    const float* w_kern_a = (const float*)d_in[6];
    const float* rel      = (const float*)d_in[7];
    const float* w_kv     = (const float*)d_in[8];
    const float* b_kv     = (const float*)d_in[9];
    const float* w_q      = (const float*)d_in[10];
    const float* b_q      = (const float*)d_in[11];
    const float* w_proj   = (const float*)d_in[12];
    const float* b_proj   = (const float*)d_in[13];
    const float* w_kern_f = (const float*)d_in[14];
    const float* w_pin    = (const float*)d_in[15];
    const float* w_dw     = (const float*)d_in[16];
    const float* w_pout   = (const float*)d_in[17];
    float* outp = (float*)d_out;

    float *p_yw, *p_q, *p_kv, *p_ao, *p_x2, *p_y2, *p_t, *p_g;
    cudaGetSymbolAddress((void**)&p_yw, g_yw);
    cudaGetSymbolAddress((void**)&p_q,  g_q);
    cudaGetSymbolAddress((void**)&p_kv, g_kv);
    cudaGetSymbolAddress((void**)&p_ao, g_ao);
    cudaGetSymbolAddress((void**)&p_x2, g_x2);
    cudaGetSymbolAddress((void**)&p_y2, g_y2);
    cudaGetSymbolAddress((void**)&p_t,  g_t);
    cudaGetSymbolAddress((void**)&p_g,  g_g);

    cudaFuncSetAttribute(attn_kernel,
                         cudaFuncAttributeMaxDynamicSharedMemorySize,
                         2 * HEADS_ * 64 * HD_ * (int)sizeof(float));

    // 1) FiLM coefficients
    film_kernel<<<B_, 360>>>(k_v, w_kern_a, w_kern_f);

    // 2) LN1 + FiLM  (NCHW -> pixel-major)
    ln_film_kernel<<<NPIX / 256, 256>>>(x, ln1_w, ln1_b, 0, p_yw);

    // 3) q / kv projections  (n-tile fast for L2 A reuse)
    dim3 gq((180 + GBN - 1) / GBN, NPIX / GBM);
    gemm_tc<0><<<gq, 256>>>(p_yw, w_q, b_q, nullptr, p_q, 180, 180);
    dim3 gkv((90 + GBN - 1) / GBN, NPIX / GBM);
    gemm_tc<0><<<gkv, 256>>>(p_yw, w_kv, b_kv, nullptr, p_kv, 90, 180);

    // 4) windowed attention
    attn_kernel<<<1024, 256, 2 * HEADS_ * 64 * HD_ * (int)sizeof(float)>>>(
        p_q, p_kv, rel, p_ao);

    // 5) proj + residual -> x2 (NCHW)
    gemm_tc<1><<<gq, 256>>>(p_ao, w_proj, b_proj, x, p_x2, 180, 180);

    // 6) LN2 + FiLM
    ln_film_kernel<<<NPIX / 256, 256>>>(p_x2, ln2_w, ln2_b, 1, p_y2);

    // 7) pin (1x1 conv, N=720)
    dim3 gp((720 + GBN - 1) / GBN, NPIX / GBM);
    gemm_tc<0><<<gp, 256>>>(p_y2, w_pin, nullptr, nullptr, p_t, 720, 180);

    // 8) depthwise 3x3 + GELU gate
    dwgate_kernel<<<NPIX, HID_>>>(p_t, w_dw, p_g);

    // 9) pout + residual -> d_out (NCHW)
    gemm_tc<1><<<gq, 256>>>(p_g, w_pout, nullptr, p_x2, outp, 180, 360);
}